// round 7
// baseline (speedup 1.0000x reference)
#include <cuda_runtime.h>
#include <cuda_bf16.h>
#include <cstdint>

#define NUM_HEADS 12
#define HD 64
#define BATCH 8
#define HH 32
#define WW 32
#define S 1024          // HH*WW
#define C 768
#define BHN 96          // BATCH*NUM_HEADS

typedef __nv_bfloat16 bf16;

// ---------------- scratch (no allocations allowed) ----------------
__device__ __align__(16) float g_q[(size_t)BHN * S * HD];
__device__ __align__(16) float g_k[(size_t)BHN * S * HD];
__device__ __align__(16) float g_v[(size_t)BHN * S * HD];
__device__ __align__(16) float g_relh[(size_t)BHN * S * HH];
__device__ __align__(16) float g_relw[(size_t)BHN * S * WW];
__device__ __align__(16) float g_att[(size_t)BATCH * S * C];

// bf16 hi/lo split copies for tensor-core GEMMs
__device__ __align__(16) bf16 gb_xh[(size_t)BATCH * S * C];
__device__ __align__(16) bf16 gb_xl[(size_t)BATCH * S * C];
__device__ __align__(16) bf16 gb_ah[(size_t)BATCH * S * C];
__device__ __align__(16) bf16 gb_al[(size_t)BATCH * S * C];
__device__ __align__(16) bf16 gb_wqh[(size_t)3 * C * C];   // [2304][768] (transposed, K-major)
__device__ __align__(16) bf16 gb_wql[(size_t)3 * C * C];
__device__ __align__(16) bf16 gb_wph[(size_t)C * C];       // [768][768] (transposed, K-major)
__device__ __align__(16) bf16 gb_wpl[(size_t)C * C];

// ---------------- fp32 -> bf16 hi/lo split (vectorized) ----------------
// in == nullptr means "read g_att"
__global__ __launch_bounds__(256) void split_kernel(const float* __restrict__ in,
                                                    bf16* __restrict__ hi,
                                                    bf16* __restrict__ lo, int n4)
{
    const float* src = in ? in : (const float*)g_att;
    int i = blockIdx.x * 256 + threadIdx.x;
    if (i >= n4) return;
    float4 a = ((const float4*)src)[i];
    bf16 h0 = __float2bfloat16(a.x), h1 = __float2bfloat16(a.y);
    bf16 h2 = __float2bfloat16(a.z), h3 = __float2bfloat16(a.w);
    bf16 l0 = __float2bfloat16(a.x - __bfloat162float(h0));
    bf16 l1 = __float2bfloat16(a.y - __bfloat162float(h1));
    bf16 l2 = __float2bfloat16(a.z - __bfloat162float(h2));
    bf16 l3 = __float2bfloat16(a.w - __bfloat162float(h3));
    __nv_bfloat162* hp = (__nv_bfloat162*)(hi + 4 * (size_t)i);
    __nv_bfloat162* lp = (__nv_bfloat162*)(lo + 4 * (size_t)i);
    __nv_bfloat162 t;
    t.x = h0; t.y = h1; hp[0] = t;
    t.x = h2; t.y = h3; hp[1] = t;
    t.x = l0; t.y = l1; lp[0] = t;
    t.x = l2; t.y = l3; lp[1] = t;
}

// transpose + split: in [K][N] fp32 -> out [N][K] bf16 hi/lo
__global__ __launch_bounds__(256) void splitT_kernel(const float* __restrict__ in,
                                                     bf16* __restrict__ hiT,
                                                     bf16* __restrict__ loT, int K, int N)
{
    __shared__ float t[32][33];
    const int k0 = blockIdx.y * 32, n0 = blockIdx.x * 32;
    const int tx = threadIdx.x, ty = threadIdx.y;   // 32 x 8
#pragma unroll
    for (int i = 0; i < 32; i += 8)
        t[ty + i][tx] = in[(size_t)(k0 + ty + i) * N + n0 + tx];
    __syncthreads();
#pragma unroll
    for (int i = 0; i < 32; i += 8) {
        const int n = n0 + ty + i, k = k0 + tx;
        const float a = t[tx][ty + i];
        bf16 h = __float2bfloat16(a);
        hiT[(size_t)n * K + k] = h;
        loT[(size_t)n * K + k] = __float2bfloat16(a - __bfloat162float(h));
    }
}

// ---------------- warp-level mma.sync split-bf16 GEMM ----------------
// C[128x128] per block, 8 warps (2m x 4n), warp tile 64x32, K chunks of 64.
// D = Ah*Bh + Ah*Bl + Al*Bh accumulated in fp32 by HMMA.
// MODE 0: scatter into g_q/g_k/g_v. MODE 1: C -> Cout row-major.
#define TSTR 72                         // smem row stride in bf16 (conflict-free)
#define TILE_B (128 * TSTR * 2)         // 18432 bytes per tile

__device__ __forceinline__ uint32_t ld32bf(const bf16* p) { return *(const uint32_t*)p; }

__device__ __forceinline__ void mma16816(float* c, const uint32_t* a, const uint32_t* b) {
    asm volatile("mma.sync.aligned.m16n8k16.row.col.f32.bf16.bf16.f32 "
                 "{%0,%1,%2,%3}, {%4,%5,%6,%7}, {%8,%9}, {%0,%1,%2,%3};"
                 : "+f"(c[0]), "+f"(c[1]), "+f"(c[2]), "+f"(c[3])
                 : "r"(a[0]), "r"(a[1]), "r"(a[2]), "r"(a[3]), "r"(b[0]), "r"(b[1]));
}

template <int MODE>
__global__ __launch_bounds__(256) void mma_gemm(const bf16* __restrict__ Ah, const bf16* __restrict__ Al,
                                                const bf16* __restrict__ Bh, const bf16* __restrict__ Bl,
                                                const float* __restrict__ bias,
                                                float* __restrict__ Cout, int Ntot)
{
    extern __shared__ char smem[];
    bf16* tiles[4];
    tiles[0] = (bf16*)(smem);                 // Ah
    tiles[1] = (bf16*)(smem + TILE_B);        // Al
    tiles[2] = (bf16*)(smem + 2 * TILE_B);    // Bh
    tiles[3] = (bf16*)(smem + 3 * TILE_B);    // Bl

    const int tid = threadIdx.x;
    const int wid = tid >> 5, lane = tid & 31;
    const int gid = lane >> 2, tig = lane & 3;      // mma fragment coords
    const int wm = wid & 1, wn = wid >> 1;          // 2 x 4 warp grid
    const int bm = blockIdx.y * 128, bn = blockIdx.x * 128;

    float acc[4][4][4];                             // [mt][nt][c0..c3]
#pragma unroll
    for (int i = 0; i < 4; i++)
#pragma unroll
        for (int j = 0; j < 4; j++)
#pragma unroll
            for (int r = 0; r < 4; r++) acc[i][j][r] = 0.f;

    const bf16* srcs[4] = { Ah, Al, Bh, Bl };

    for (int kc = 0; kc < 12; kc++) {
        const int k0 = kc * 64;
        // stage 4 tiles: 128 rows x 64 bf16 each = 1024 uint4 per tile, 4 per thread
#pragma unroll
        for (int mtx = 0; mtx < 4; mtx++) {
            const bf16* src = srcs[mtx];
            const int rowbase = (mtx < 2) ? bm : bn;
            bf16* dst = tiles[mtx];
#pragma unroll
            for (int u = 0; u < 4; u++) {
                const int idx = tid + 256 * u;
                const int r = idx >> 3, c4 = idx & 7;
                uint4 v = *(const uint4*)(src + (size_t)(rowbase + r) * 768 + k0 + c4 * 8);
                *(uint4*)(dst + r * TSTR + c4 * 8) = v;
            }
        }
        __syncthreads();

        const bf16* pAh = tiles[0] + (wm * 64 + gid) * TSTR + tig * 2;
        const bf16* pAl = tiles[1] + (wm * 64 + gid) * TSTR + tig * 2;
        const bf16* pBh = tiles[2] + (wn * 32 + gid) * TSTR + tig * 2;
        const bf16* pBl = tiles[3] + (wn * 32 + gid) * TSTR + tig * 2;

#pragma unroll
        for (int ks = 0; ks < 4; ks++) {
            const int ko = ks * 16;
            uint32_t ah[4][4], al[4][4], bh[4][2], bl[4][2];
#pragma unroll
            for (int mt = 0; mt < 4; mt++) {
                const bf16* p = pAh + mt * (16 * TSTR) + ko;
                ah[mt][0] = ld32bf(p);
                ah[mt][1] = ld32bf(p + 8 * TSTR);
                ah[mt][2] = ld32bf(p + 8);
                ah[mt][3] = ld32bf(p + 8 * TSTR + 8);
                const bf16* q = pAl + mt * (16 * TSTR) + ko;
                al[mt][0] = ld32bf(q);
                al[mt][1] = ld32bf(q + 8 * TSTR);
                al[mt][2] = ld32bf(q + 8);
                al[mt][3] = ld32bf(q + 8 * TSTR + 8);
            }
#pragma unroll
            for (int nt = 0; nt < 4; nt++) {
                const bf16* p = pBh + nt * (8 * TSTR) + ko;
                bh[nt][0] = ld32bf(p);
                bh[nt][1] = ld32bf(p + 8);
                const bf16* q = pBl + nt * (8 * TSTR) + ko;
                bl[nt][0] = ld32bf(q);
                bl[nt][1] = ld32bf(q + 8);
            }
#pragma unroll
            for (int mt = 0; mt < 4; mt++)
#pragma unroll
                for (int nt = 0; nt < 4; nt++) {
                    mma16816(acc[mt][nt], ah[mt], bh[nt]);
                    mma16816(acc[mt][nt], ah[mt], bl[nt]);
                    mma16816(acc[mt][nt], al[mt], bh[nt]);
                }
        }
        __syncthreads();
    }

    // epilogue: rows bm+wm*64+mt*16+gid(+8), cols bn+wn*32+nt*8+tig*2(+1)
#pragma unroll
    for (int mt = 0; mt < 4; mt++) {
#pragma unroll
        for (int half = 0; half < 2; half++) {
            const int m = bm + wm * 64 + mt * 16 + gid + half * 8;
            const int b = m >> 10, s = m & 1023;
#pragma unroll
            for (int nt = 0; nt < 4; nt++) {
                const int n = bn + wn * 32 + nt * 8 + tig * 2;
                const float v0 = acc[mt][nt][half * 2 + 0] + bias[n];
                const float v1 = acc[mt][nt][half * 2 + 1] + bias[n + 1];
                if (MODE == 0) {
                    const int t   = n / C;
                    const int rem = n - t * C;
                    const int hh  = rem >> 6, d = rem & 63;   // pair stays in-head (n even)
                    float* dst = (t == 0) ? g_q : (t == 1) ? g_k : g_v;
                    float2 st; st.x = v0; st.y = v1;
                    *(float2*)(dst + ((size_t)(b * NUM_HEADS + hh) * S + s) * HD + d) = st;
                } else {
                    float2 st; st.x = v0; st.y = v1;
                    *(float2*)(Cout + (size_t)m * Ntot + n) = st;
                }
            }
        }
    }
}

// ---------------- relative-position bias tables ----------------
__global__ __launch_bounds__(128) void rel_kernel(const float* __restrict__ table, int mode)
{
    __shared__ float tab[63][65];
    __shared__ float qs[32][65];
    const int bh = blockIdx.y;
    const int h  = blockIdx.x;
    const int tid = threadIdx.x;

    for (int idx = tid; idx < 63 * 64; idx += 128)
        tab[idx >> 6][idx & 63] = table[idx];
    const float* qbase = g_q + ((size_t)bh * S + h * 32) * HD;
    for (int idx = tid; idx < 32 * 64; idx += 128)
        qs[idx >> 6][idx & 63] = qbase[idx];
    __syncthreads();

    float* out = (mode == 0) ? g_relh : g_relw;
    float* obase = out + ((size_t)bh * 32 + h) * 32 * 32;

    for (int o = tid; o < 1024; o += 128) {
        const int w = o >> 5, j = o & 31;
        const int row = (mode == 0) ? (h - j + 31) : (w - j + 31);
        const float* qr = qs[w];
        const float* tr = tab[row];
        float a0 = 0.f, a1 = 0.f, a2 = 0.f, a3 = 0.f;
#pragma unroll
        for (int d = 0; d < 64; d += 4) {
            a0 = fmaf(qr[d + 0], tr[d + 0], a0);
            a1 = fmaf(qr[d + 1], tr[d + 1], a1);
            a2 = fmaf(qr[d + 2], tr[d + 2], a2);
            a3 = fmaf(qr[d + 3], tr[d + 3], a3);
        }
        obase[o] = (a0 + a1) + (a2 + a3);
    }
}

// ---------------- fused attention (R3 best: scalar FFMA) ----------------
struct AttSmem {
    float q [128][65];
    float sc[128][33];
    float kv[32][65];
    float rws[128][33];
    float corr[128];
    float invl[128];
};

__global__ __launch_bounds__(128) void attn_kernel()
{
    extern __shared__ char smem_raw[];
    AttSmem& sm = *reinterpret_cast<AttSmem*>(smem_raw);

    const int bh  = blockIdx.y;
    const int s0  = blockIdx.x * 128;
    const int tid = threadIdx.x;
    const int qty = tid >> 3;
    const int qtx = tid & 7;
    const float scale = 0.125f;

    {
        const float4* qp = (const float4*)(g_q + ((size_t)bh * S + s0) * HD);
#pragma unroll
        for (int u = 0; u < 16; u++) {
            const int idx4 = tid + 128 * u;
            float4 t = qp[idx4];
            const int r = idx4 >> 4, c = (idx4 & 15) * 4;
            sm.q[r][c + 0] = t.x * scale;
            sm.q[r][c + 1] = t.y * scale;
            sm.q[r][c + 2] = t.z * scale;
            sm.q[r][c + 3] = t.w * scale;
        }
    }
    {
        const float* rp = g_relw + ((size_t)bh * S + s0) * 32;
        for (int idx = tid; idx < 128 * 32; idx += 128)
            sm.rws[idx >> 5][idx & 31] = rp[idx];
    }

    float o[8][8];
#pragma unroll
    for (int i = 0; i < 8; i++)
#pragma unroll
        for (int j = 0; j < 8; j++) o[i][j] = 0.f;

    float mrun = -1e30f, lrun = 0.f;

    for (int kt0 = 0; kt0 < S; kt0 += 32) {
        __syncthreads();
        {
            const float4* kp = (const float4*)(g_k + ((size_t)bh * S + kt0) * HD);
            float4 kreg[4];
#pragma unroll
            for (int u = 0; u < 4; u++) kreg[u] = kp[tid + 128 * u];
#pragma unroll
            for (int u = 0; u < 4; u++) {
                const int idx4 = tid + 128 * u;
                const int r = idx4 >> 4, c = (idx4 & 15) * 4;
                sm.kv[r][c + 0] = kreg[u].x;
                sm.kv[r][c + 1] = kreg[u].y;
                sm.kv[r][c + 2] = kreg[u].z;
                sm.kv[r][c + 3] = kreg[u].w;
            }
        }
        __syncthreads();

        {
            float acc[8][4];
#pragma unroll
            for (int i = 0; i < 8; i++)
#pragma unroll
                for (int j = 0; j < 4; j++) acc[i][j] = 0.f;

#pragma unroll 8
            for (int kk = 0; kk < 64; kk++) {
                float a[8], b[4];
#pragma unroll
                for (int i = 0; i < 8; i++) a[i] = sm.q[qty * 8 + i][kk];
#pragma unroll
                for (int j = 0; j < 4; j++) b[j] = sm.kv[qtx * 4 + j][kk];
#pragma unroll
                for (int i = 0; i < 8; i++)
#pragma unroll
                    for (int j = 0; j < 4; j++)
                        acc[i][j] = fmaf(a[i], b[j], acc[i][j]);
            }
#pragma unroll
            for (int i = 0; i < 8; i++)
#pragma unroll
                for (int j = 0; j < 4; j++)
                    sm.sc[qty * 8 + i][qtx * 4 + j] = acc[i][j];
        }
        __syncthreads();

        {
            const float4* vp = (const float4*)(g_v + ((size_t)bh * S + kt0) * HD);
            float4 vreg[4];
#pragma unroll
            for (int u = 0; u < 4; u++) vreg[u] = vp[tid + 128 * u];

            const float rhb = g_relh[((size_t)bh * S + s0 + tid) * 32 + (kt0 >> 5)];
            float s[32];
            float mt = -1e30f;
#pragma unroll
            for (int j = 0; j < 32; j++) {
                s[j] = sm.sc[tid][j] + sm.rws[tid][j] + rhb;
                mt = fmaxf(mt, s[j]);
            }
            const float mnew = fmaxf(mrun, mt);
            const float cf = __expf(mrun - mnew);
            lrun *= cf;
#pragma unroll
            for (int j = 0; j < 32; j++) {
                const float p = __expf(s[j] - mnew);
                lrun += p;
                sm.sc[tid][j] = p;
            }
            mrun = mnew;
            sm.corr[tid] = cf;
            if (kt0 == S - 32) sm.invl[tid] = 1.f / lrun;

#pragma unroll
            for (int u = 0; u < 4; u++) {
                const int idx4 = tid + 128 * u;
                const int r = idx4 >> 4, c = (idx4 & 15) * 4;
                sm.kv[r][c + 0] = vreg[u].x;
                sm.kv[r][c + 1] = vreg[u].y;
                sm.kv[r][c + 2] = vreg[u].z;
                sm.kv[r][c + 3] = vreg[u].w;
            }
        }
        __syncthreads();

        {
            float c8[8];
#pragma unroll
            for (int i = 0; i < 8; i++) c8[i] = sm.corr[qty * 8 + i];
#pragma unroll
            for (int i = 0; i < 8; i++)
#pragma unroll
                for (int j = 0; j < 8; j++) o[i][j] *= c8[i];

#pragma unroll 4
            for (int key = 0; key < 32; key++) {
                float vv[8];
#pragma unroll
                for (int j = 0; j < 4; j++) vv[j]     = sm.kv[key][qtx * 4 + j];
#pragma unroll
                for (int j = 0; j < 4; j++) vv[4 + j] = sm.kv[key][32 + qtx * 4 + j];
#pragma unroll
                for (int i = 0; i < 8; i++) {
                    const float p = sm.sc[qty * 8 + i][key];
#pragma unroll
                    for (int j = 0; j < 8; j++)
                        o[i][j] = fmaf(p, vv[j], o[i][j]);
                }
            }
        }
    }

    {
        float inv8[8];
#pragma unroll
        for (int i = 0; i < 8; i++) inv8[i] = sm.invl[qty * 8 + i];
        const int b = bh / NUM_HEADS, head = bh % NUM_HEADS;
#pragma unroll
        for (int i = 0; i < 8; i++) {
            const int qrow = s0 + qty * 8 + i;
            float* dst = g_att + ((size_t)(b * S + qrow)) * C + head * HD;
            float4 t0, t1;
            t0.x = o[i][0] * inv8[i];
            t0.y = o[i][1] * inv8[i];
            t0.z = o[i][2] * inv8[i];
            t0.w = o[i][3] * inv8[i];
            t1.x = o[i][4] * inv8[i];
            t1.y = o[i][5] * inv8[i];
            t1.z = o[i][6] * inv8[i];
            t1.w = o[i][7] * inv8[i];
            *(float4*)(dst + qtx * 4)      = t0;
            *(float4*)(dst + 32 + qtx * 4) = t1;
        }
    }
}

// ---------------- launch ----------------
extern "C" void kernel_launch(void* const* d_in, const int* in_sizes, int n_in,
                              void* d_out, int out_size)
{
    const float* x     = (const float*)d_in[0];
    const float* wqkv  = (const float*)d_in[1];
    const float* bqkv  = (const float*)d_in[2];
    const float* rph   = (const float*)d_in[3];
    const float* rpw   = (const float*)d_in[4];
    const float* wproj = (const float*)d_in[5];
    const float* bproj = (const float*)d_in[6];
    float* out = (float*)d_out;

    const int GEMM_SMEM = 4 * TILE_B;   // 73728
    cudaFuncSetAttribute(mma_gemm<0>, cudaFuncAttributeMaxDynamicSharedMemorySize, GEMM_SMEM);
    cudaFuncSetAttribute(mma_gemm<1>, cudaFuncAttributeMaxDynamicSharedMemorySize, GEMM_SMEM);

    // 0) split fp32 -> bf16 hi/lo
    const int n4 = BATCH * S * C / 4;
    split_kernel<<<(n4 + 255) / 256, 256>>>(x, gb_xh, gb_xl, n4);
    splitT_kernel<<<dim3(3 * C / 32, C / 32), dim3(32, 8)>>>(wqkv, gb_wqh, gb_wql, C, 3 * C);
    splitT_kernel<<<dim3(C / 32, C / 32), dim3(32, 8)>>>(wproj, gb_wph, gb_wpl, C, C);

    // 1) QKV GEMM on tensor cores (mma.sync) -> g_q/g_k/g_v
    mma_gemm<0><<<dim3(3 * C / 128, BATCH * S / 128), 256, GEMM_SMEM>>>(
        gb_xh, gb_xl, gb_wqh, gb_wql, bqkv, nullptr, 3 * C);

    // 2) relative-position bias tables
    rel_kernel<<<dim3(32, BHN), 128>>>(rph, 0);
    rel_kernel<<<dim3(32, BHN), 128>>>(rpw, 1);

    // 3) fused attention -> g_att
    const size_t attn_smem = sizeof(AttSmem);
    cudaFuncSetAttribute(attn_kernel, cudaFuncAttributeMaxDynamicSharedMemorySize,
                         (int)attn_smem);
    attn_kernel<<<dim3(S / 128, BHN), 128, attn_smem>>>();

    // 4) split attention output, then proj GEMM -> d_out
    split_kernel<<<(n4 + 255) / 256, 256>>>(nullptr, gb_ah, gb_al, n4);
    mma_gemm<1><<<dim3(C / 128, BATCH * S / 128), 256, GEMM_SMEM>>>(
        gb_ah, gb_al, gb_wph, gb_wpl, bproj, out, C);
}

// round 8
// speedup vs baseline: 4.8753x; 4.8753x over previous
#include <cuda_runtime.h>

#define NUM_HEADS 12
#define HD 64
#define BATCH 8
#define HH 32
#define WW 32
#define S 1024          // HH*WW
#define C 768
#define BHN 96          // BATCH*NUM_HEADS

// ---------------- scratch (no allocations allowed) ----------------
__device__ __align__(16) float g_q[(size_t)BHN * S * HD];
__device__ __align__(16) float g_k[(size_t)BHN * S * HD];
__device__ __align__(16) float g_v[(size_t)BHN * S * HD];
__device__ __align__(16) float g_relh[(size_t)BHN * S * HH];
__device__ __align__(16) float g_relw[(size_t)BHN * S * WW];
__device__ __align__(16) float g_att[(size_t)BATCH * S * C];

// ---------------- 128x128x8 fp32 GEMM, 8x8 microtile, reg double-buffer ----
// MODE 0: C = A @ B + bias, scatter into g_q/g_k/g_v  (A = x, B = w_qkv)
// MODE 1: C = g_att @ B + bias -> Cout (row-major)     (B = w_proj)
template <int MODE>
__global__ __launch_bounds__(256) void gemm_k(const float* __restrict__ A,
                                              const float* __restrict__ B,
                                              const float* __restrict__ bias,
                                              float* __restrict__ Cout,
                                              int M, int N, int K)
{
    __shared__ __align__(16) float As[8][128];
    __shared__ __align__(16) float Bs[8][128];

    const float* Ap = (MODE == 1) ? (const float*)g_att : A;

    const int tid = threadIdx.x;
    const int tx = tid & 15, ty = tid >> 4;
    const int bm = blockIdx.y * 128, bn = blockIdx.x * 128;

    float acc[8][8];
#pragma unroll
    for (int i = 0; i < 8; i++)
#pragma unroll
        for (int j = 0; j < 8; j++) acc[i][j] = 0.f;

    const int arow = tid >> 1, acol = (tid & 1) * 4;
    const int brow = tid >> 5, bcol = (tid & 31) * 4;

    // preload chunk 0 into registers
    float4 av = *(const float4*)(Ap + (size_t)(bm + arow) * K + acol);
    float4 bv = *(const float4*)(B + (size_t)brow * N + bn + bcol);

    for (int k0 = 0; k0 < K; k0 += 8) {
        // store staged chunk to smem
        As[acol + 0][arow] = av.x;
        As[acol + 1][arow] = av.y;
        As[acol + 2][arow] = av.z;
        As[acol + 3][arow] = av.w;
        *(float4*)&Bs[brow][bcol] = bv;

        // prefetch next chunk (LDG in flight across sync + compute)
        const int kn = (k0 + 8 < K) ? k0 + 8 : k0;
        av = *(const float4*)(Ap + (size_t)(bm + arow) * K + kn + acol);
        bv = *(const float4*)(B + (size_t)(kn + brow) * N + bn + bcol);

        __syncthreads();
#pragma unroll
        for (int kk = 0; kk < 8; kk++) {
            float a[8], b[8];
            *(float4*)(a)     = *(const float4*)&As[kk][ty * 8];
            *(float4*)(a + 4) = *(const float4*)&As[kk][ty * 8 + 4];
            *(float4*)(b)     = *(const float4*)&Bs[kk][tx * 8];
            *(float4*)(b + 4) = *(const float4*)&Bs[kk][tx * 8 + 4];
#pragma unroll
            for (int i = 0; i < 8; i++)
#pragma unroll
                for (int j = 0; j < 8; j++)
                    acc[i][j] = fmaf(a[i], b[j], acc[i][j]);
        }
        __syncthreads();
    }

#pragma unroll
    for (int i = 0; i < 8; i++) {
        const int m = bm + ty * 8 + i;
        const int b = m >> 10, s = m & 1023;
#pragma unroll
        for (int j = 0; j < 8; j++) {
            const int n = bn + tx * 8 + j;
            const float v = acc[i][j] + bias[n];
            if (MODE == 0) {
                const int t   = n / C;          // 0:q 1:k 2:v
                const int rem = n - t * C;
                const int hh  = rem >> 6;       // head
                const int d   = rem & 63;
                float* dst = (t == 0) ? g_q : (t == 1) ? g_k : g_v;
                dst[((size_t)(b * NUM_HEADS + hh) * S + s) * HD + d] = v;
            } else {
                Cout[(size_t)m * N + n] = v;
            }
        }
    }
}

// ---------------- relative-position bias tables (256 threads) -------------
__global__ __launch_bounds__(256) void rel_kernel(const float* __restrict__ table, int mode)
{
    __shared__ float tab[63][65];
    __shared__ float qs[32][65];
    const int bh = blockIdx.y;
    const int h  = blockIdx.x;
    const int tid = threadIdx.x;

    for (int idx = tid; idx < 63 * 64; idx += 256)
        tab[idx >> 6][idx & 63] = table[idx];
    const float* qbase = g_q + ((size_t)bh * S + h * 32) * HD;
    for (int idx = tid; idx < 32 * 64; idx += 256)
        qs[idx >> 6][idx & 63] = qbase[idx];
    __syncthreads();

    float* out = (mode == 0) ? g_relh : g_relw;
    float* obase = out + ((size_t)bh * 32 + h) * 32 * 32;

    for (int o = tid; o < 1024; o += 256) {
        const int w = o >> 5, j = o & 31;
        const int row = (mode == 0) ? (h - j + 31) : (w - j + 31);
        const float* qr = qs[w];
        const float* tr = tab[row];
        float a0 = 0.f, a1 = 0.f, a2 = 0.f, a3 = 0.f;
#pragma unroll
        for (int d = 0; d < 64; d += 4) {
            a0 = fmaf(qr[d + 0], tr[d + 0], a0);
            a1 = fmaf(qr[d + 1], tr[d + 1], a1);
            a2 = fmaf(qr[d + 2], tr[d + 2], a2);
            a3 = fmaf(qr[d + 3], tr[d + 3], a3);
        }
        obase[o] = (a0 + a1) + (a2 + a3);
    }
}

// ---------------- fused attention: R3 structure + K-tile reg prefetch -----
struct AttSmem {
    float q [128][65];
    float sc[128][33];
    float kv[32][65];
    float rws[128][33];
    float corr[128];
    float invl[128];
};

__global__ __launch_bounds__(128) void attn_kernel()
{
    extern __shared__ char smem_raw[];
    AttSmem& sm = *reinterpret_cast<AttSmem*>(smem_raw);

    const int bh  = blockIdx.y;
    const int s0  = blockIdx.x * 128;
    const int tid = threadIdx.x;
    const int qty = tid >> 3;
    const int qtx = tid & 7;
    const float scale = 0.125f;

    {
        const float4* qp = (const float4*)(g_q + ((size_t)bh * S + s0) * HD);
#pragma unroll
        for (int u = 0; u < 16; u++) {
            const int idx4 = tid + 128 * u;
            float4 t = qp[idx4];
            const int r = idx4 >> 4, c = (idx4 & 15) * 4;
            sm.q[r][c + 0] = t.x * scale;
            sm.q[r][c + 1] = t.y * scale;
            sm.q[r][c + 2] = t.z * scale;
            sm.q[r][c + 3] = t.w * scale;
        }
    }
    {
        const float* rp = g_relw + ((size_t)bh * S + s0) * 32;
        for (int idx = tid; idx < 128 * 32; idx += 128)
            sm.rws[idx >> 5][idx & 31] = rp[idx];
    }

    float o[8][8];
#pragma unroll
    for (int i = 0; i < 8; i++)
#pragma unroll
        for (int j = 0; j < 8; j++) o[i][j] = 0.f;

    float mrun = -1e30f, lrun = 0.f;

    // preload K tile 0 into registers
    float4 kreg[4];
    {
        const float4* kp = (const float4*)(g_k + ((size_t)bh * S) * HD);
#pragma unroll
        for (int u = 0; u < 4; u++) kreg[u] = kp[tid + 128 * u];
    }

    for (int kt0 = 0; kt0 < S; kt0 += 32) {
        __syncthreads();            // kv free (prev PV done; iter0: staging done)

        // ---- stage prefetched K tile ----
#pragma unroll
        for (int u = 0; u < 4; u++) {
            const int idx4 = tid + 128 * u;
            const int r = idx4 >> 4, c = (idx4 & 15) * 4;
            sm.kv[r][c + 0] = kreg[u].x;
            sm.kv[r][c + 1] = kreg[u].y;
            sm.kv[r][c + 2] = kreg[u].z;
            sm.kv[r][c + 3] = kreg[u].w;
        }
        __syncthreads();

        // ---- QK micro-tile: 8q x 4k ----
        {
            float acc[8][4];
#pragma unroll
            for (int i = 0; i < 8; i++)
#pragma unroll
                for (int j = 0; j < 4; j++) acc[i][j] = 0.f;

#pragma unroll 8
            for (int kk = 0; kk < 64; kk++) {
                float a[8], b[4];
#pragma unroll
                for (int i = 0; i < 8; i++) a[i] = sm.q[qty * 8 + i][kk];
#pragma unroll
                for (int j = 0; j < 4; j++) b[j] = sm.kv[qtx * 4 + j][kk];
#pragma unroll
                for (int i = 0; i < 8; i++)
#pragma unroll
                    for (int j = 0; j < 4; j++)
                        acc[i][j] = fmaf(a[i], b[j], acc[i][j]);
            }
#pragma unroll
            for (int i = 0; i < 8; i++)
#pragma unroll
                for (int j = 0; j < 4; j++)
                    sm.sc[qty * 8 + i][qtx * 4 + j] = acc[i][j];
        }
        __syncthreads();

        // ---- softmax + V prefetch + next-K prefetch ----
        {
            const float4* vp = (const float4*)(g_v + ((size_t)bh * S + kt0) * HD);
            float4 vreg[4];
#pragma unroll
            for (int u = 0; u < 4; u++) vreg[u] = vp[tid + 128 * u];

            // prefetch next K tile (registers; consumed at next loop head)
            const int ktn = (kt0 + 32 < S) ? kt0 + 32 : kt0;
            const float4* kp = (const float4*)(g_k + ((size_t)bh * S + ktn) * HD);
#pragma unroll
            for (int u = 0; u < 4; u++) kreg[u] = kp[tid + 128 * u];

            const float rhb = g_relh[((size_t)bh * S + s0 + tid) * 32 + (kt0 >> 5)];
            float s[32];
            float mt = -1e30f;
#pragma unroll
            for (int j = 0; j < 32; j++) {
                s[j] = sm.sc[tid][j] + sm.rws[tid][j] + rhb;
                mt = fmaxf(mt, s[j]);
            }
            const float mnew = fmaxf(mrun, mt);
            const float cf = __expf(mrun - mnew);
            lrun *= cf;
#pragma unroll
            for (int j = 0; j < 32; j++) {
                const float p = __expf(s[j] - mnew);
                lrun += p;
                sm.sc[tid][j] = p;
            }
            mrun = mnew;
            sm.corr[tid] = cf;
            if (kt0 == S - 32) sm.invl[tid] = 1.f / lrun;

            // stage V (QK reads of kv finished before last sync)
#pragma unroll
            for (int u = 0; u < 4; u++) {
                const int idx4 = tid + 128 * u;
                const int r = idx4 >> 4, c = (idx4 & 15) * 4;
                sm.kv[r][c + 0] = vreg[u].x;
                sm.kv[r][c + 1] = vreg[u].y;
                sm.kv[r][c + 2] = vreg[u].z;
                sm.kv[r][c + 3] = vreg[u].w;
            }
        }
        __syncthreads();

        // ---- PV micro-tile: 8q x 8d ----
        {
            float c8[8];
#pragma unroll
            for (int i = 0; i < 8; i++) c8[i] = sm.corr[qty * 8 + i];
#pragma unroll
            for (int i = 0; i < 8; i++)
#pragma unroll
                for (int j = 0; j < 8; j++) o[i][j] *= c8[i];

#pragma unroll 4
            for (int key = 0; key < 32; key++) {
                float vv[8];
#pragma unroll
                for (int j = 0; j < 4; j++) vv[j]     = sm.kv[key][qtx * 4 + j];
#pragma unroll
                for (int j = 0; j < 4; j++) vv[4 + j] = sm.kv[key][32 + qtx * 4 + j];
#pragma unroll
                for (int i = 0; i < 8; i++) {
                    const float p = sm.sc[qty * 8 + i][key];
#pragma unroll
                    for (int j = 0; j < 8; j++)
                        o[i][j] = fmaf(p, vv[j], o[i][j]);
                }
            }
        }
    }

    // ---- epilogue ----
    {
        float inv8[8];
#pragma unroll
        for (int i = 0; i < 8; i++) inv8[i] = sm.invl[qty * 8 + i];
        const int b = bh / NUM_HEADS, head = bh % NUM_HEADS;
#pragma unroll
        for (int i = 0; i < 8; i++) {
            const int qrow = s0 + qty * 8 + i;
            float* dst = g_att + ((size_t)(b * S + qrow)) * C + head * HD;
            float4 t0, t1;
            t0.x = o[i][0] * inv8[i];
            t0.y = o[i][1] * inv8[i];
            t0.z = o[i][2] * inv8[i];
            t0.w = o[i][3] * inv8[i];
            t1.x = o[i][4] * inv8[i];
            t1.y = o[i][5] * inv8[i];
            t1.z = o[i][6] * inv8[i];
            t1.w = o[i][7] * inv8[i];
            *(float4*)(dst + qtx * 4)      = t0;
            *(float4*)(dst + 32 + qtx * 4) = t1;
        }
    }
}

// ---------------- launch ----------------
extern "C" void kernel_launch(void* const* d_in, const int* in_sizes, int n_in,
                              void* d_out, int out_size)
{
    const float* x     = (const float*)d_in[0];
    const float* wqkv  = (const float*)d_in[1];
    const float* bqkv  = (const float*)d_in[2];
    const float* rph   = (const float*)d_in[3];
    const float* rpw   = (const float*)d_in[4];
    const float* wproj = (const float*)d_in[5];
    const float* bproj = (const float*)d_in[6];
    float* out = (float*)d_out;

    // 1) QKV GEMM -> g_q/g_k/g_v  (M=8192, N=2304, K=768)
    dim3 g1(2304 / 128, 8192 / 128);
    gemm_k<0><<<g1, 256>>>(x, wqkv, bqkv, nullptr, BATCH * S, 3 * C, C);

    // 2) relative-position bias tables
    rel_kernel<<<dim3(32, BHN), 256>>>(rph, 0);
    rel_kernel<<<dim3(32, BHN), 256>>>(rpw, 1);

    // 3) fused attention -> g_att
    const size_t attn_smem = sizeof(AttSmem);
    cudaFuncSetAttribute(attn_kernel, cudaFuncAttributeMaxDynamicSharedMemorySize,
                         (int)attn_smem);
    attn_kernel<<<dim3(S / 128, BHN), 128, attn_smem>>>();

    // 4) output projection -> d_out  (M=8192, N=768, K=768)
    dim3 g2(768 / 128, 8192 / 128);
    gemm_k<1><<<g2, 256>>>(nullptr, wproj, bproj, out, BATCH * S, C, C);
}